// round 15
// baseline (speedup 1.0000x reference)
#include <cuda_runtime.h>
#include <cuda_fp16.h>
#include <cstdint>
#include <math.h>

#define D_HID 2048
#define INTER 1408
#define NGU   2816
#define NEXP  8
#define TMAX  4096
#define TPAIR 8192
#define RMAX  9216

// ---------------- device scratch ----------------
__device__ int   g_count[NEXP];
__device__ int   g_top_e[TPAIR];
__device__ int   g_pos[TPAIR];
__device__ int   g_s2t[RMAX];
__device__ float g_swt[RMAX];
__device__ float g_wt[TPAIR];
__device__ __align__(256) __half g_x16 [(size_t)TMAX * D_HID];
__device__ __align__(256) __half g_gup [(size_t)NEXP * NGU * D_HID];
__device__ __align__(256) __half g_dwn [(size_t)NEXP * D_HID * INTER];
__device__ __align__(256) __half g_h   [(size_t)RMAX * INTER];

// ---------------- helpers ----------------
__device__ __forceinline__ uint32_t smem_u32(const void* p) {
    uint32_t a;
    asm("{ .reg .u64 t; cvta.to.shared.u64 t, %1; cvt.u32.u64 %0, t; }" : "=r"(a) : "l"(p));
    return a;
}
__device__ __forceinline__ void cp16z(uint32_t dst, const void* src, uint32_t sz) {
    asm volatile("cp.async.cg.shared.global [%0], [%1], 16, %2;"
                 :: "r"(dst), "l"(src), "r"(sz));
}
__device__ __forceinline__ void ldsm4(uint32_t* r, uint32_t addr) {
    asm volatile("ldmatrix.sync.aligned.m8n8.x4.shared.b16 {%0,%1,%2,%3}, [%4];"
                 : "=r"(r[0]), "=r"(r[1]), "=r"(r[2]), "=r"(r[3]) : "r"(addr));
}
__device__ __forceinline__ void mma_f16(float* d, const uint32_t* a, const uint32_t* b) {
    asm volatile("mma.sync.aligned.m16n8k16.row.col.f32.f16.f16.f32 "
                 "{%0,%1,%2,%3}, {%4,%5,%6,%7}, {%8,%9}, {%0,%1,%2,%3};"
                 : "+f"(d[0]), "+f"(d[1]), "+f"(d[2]), "+f"(d[3])
                 : "r"(a[0]), "r"(a[1]), "r"(a[2]), "r"(a[3]), "r"(b[0]), "r"(b[1]));
}
__device__ __forceinline__ int expert_base(int e) {
    int o = 0;
#pragma unroll
    for (int k = 0; k < NEXP; k++)
        if (k < e) o += (g_count[k] + 127) & ~127;
    return o;
}
__device__ __forceinline__ uint4 pack8(float4 a, float4 b) {
    uint4 o;
    __half2 h0 = __floats2half2_rn(a.x, a.y);
    __half2 h1 = __floats2half2_rn(a.z, a.w);
    __half2 h2 = __floats2half2_rn(b.x, b.y);
    __half2 h3 = __floats2half2_rn(b.z, b.w);
    o.x = *reinterpret_cast<uint32_t*>(&h0);
    o.y = *reinterpret_cast<uint32_t*>(&h1);
    o.z = *reinterpret_cast<uint32_t*>(&h2);
    o.w = *reinterpret_cast<uint32_t*>(&h3);
    return o;
}

// ---------------- zero: counts + out ----------------
__global__ void zero_kernel(float4* __restrict__ out, int n4) {
    int i = blockIdx.x * blockDim.x + threadIdx.x;
    if (blockIdx.x == 0 && threadIdx.x < NEXP) g_count[threadIdx.x] = 0;
    if (i < n4) out[i] = make_float4(0.f, 0.f, 0.f, 0.f);
}

// ---------------- fused prep + router ----------------
#define GUP_ROWS (NEXP*NGU)    // 22528
#define DWN_ROWS (NEXP*D_HID)  // 16384
__global__ void prep_router_kernel(const float* __restrict__ x,
                                   const float* __restrict__ rw,
                                   const float* __restrict__ gup,
                                   const float* __restrict__ dwn) {
    int b = blockIdx.x;
    int i = threadIdx.x;       // 256
    if (b < GUP_ROWS) {
        int e = b / NGU;
        int n = b % NGU;
        int blk = n >> 6, r = n & 63;
        int src_n = (r < 32) ? (blk*32 + r) : (INTER + blk*32 + (r - 32));
        const float4* src = (const float4*)(gup + ((size_t)e * NGU + src_n) * D_HID);
        float4 a = src[2*i], c = src[2*i + 1];
        ((uint4*)(g_gup + (size_t)b * D_HID))[i] = pack8(a, c);
    } else if (b < GUP_ROWS + DWN_ROWS) {
        int row = b - GUP_ROWS;
        if (i < INTER/8) {
            const float4* src = (const float4*)(dwn + (size_t)row * INTER);
            float4 a = src[2*i], c = src[2*i + 1];
            ((uint4*)(g_dwn + (size_t)row * INTER))[i] = pack8(a, c);
        }
    } else {
        // router block: one token
        int t = b - GUP_ROWS - DWN_ROWS;
        const float4* x4 = (const float4*)(x + (size_t)t * D_HID);
        float4 v0 = x4[2*i];
        float4 v1 = x4[2*i + 1];
        ((uint4*)(g_x16 + (size_t)t * D_HID))[i] = pack8(v0, v1);

        float p[NEXP];
#pragma unroll
        for (int e = 0; e < NEXP; e++) {
            const float4* r4 = (const float4*)(rw + (size_t)e * D_HID);
            float4 w0 = r4[2*i];
            float4 w1 = r4[2*i + 1];
            float s = v0.x * w0.x;
            s = fmaf(v0.y, w0.y, s);
            s = fmaf(v0.z, w0.z, s);
            s = fmaf(v0.w, w0.w, s);
            s = fmaf(v1.x, w1.x, s);
            s = fmaf(v1.y, w1.y, s);
            s = fmaf(v1.z, w1.z, s);
            s = fmaf(v1.w, w1.w, s);
            p[e] = s;
        }
#pragma unroll
        for (int off = 16; off > 0; off >>= 1)
#pragma unroll
            for (int e = 0; e < NEXP; e++)
                p[e] += __shfl_down_sync(0xffffffffu, p[e], off);
        __shared__ float s[8][NEXP];
        int warp = i >> 5;
        if ((i & 31) == 0)
#pragma unroll
            for (int e = 0; e < NEXP; e++) s[warp][e] = p[e];
        __syncthreads();
        if (i == 0) {
            float l[NEXP];
#pragma unroll
            for (int e = 0; e < NEXP; e++) {
                float a = 0.f;
#pragma unroll
                for (int w = 0; w < 8; w++) a += s[w][e];
                l[e] = a;
            }
            int i0 = 0;
#pragma unroll
            for (int e = 1; e < NEXP; e++) if (l[e] > l[i0]) i0 = e;
            int i1 = (i0 == 0) ? 1 : 0;
#pragma unroll
            for (int e = 0; e < NEXP; e++)
                if (e != i0 && l[e] > l[i1]) i1 = e;
            float e1  = expf(l[i1] - l[i0]);
            float inv = 1.f / (1.f + e1);
            g_wt[2*t]   = inv;
            g_wt[2*t+1] = e1 * inv;
            int p0 = atomicAdd(&g_count[i0], 1);
            g_top_e[2*t] = i0; g_pos[2*t] = p0;
            int p1 = atomicAdd(&g_count[i1], 1);
            g_top_e[2*t+1] = i1; g_pos[2*t+1] = p1;
        }
    }
}

// ---------------- map: slot -> (token, weight) ----------------
__global__ void map_kernel() {
    int p = blockIdx.x * blockDim.x + threadIdx.x;
    if (p < TPAIR) {
        int sidx = expert_base(g_top_e[p]) + g_pos[p];
        g_s2t[sidx] = p >> 1;
        g_swt[sidx] = g_wt[p];
    }
}

// ---------------- HMMA grouped GEMM (pure fp16, SW128, hoisted indexing) ---
// CTA tile 128x128, 256 threads (8 warps: 4 in M x 2 in N), 2 CTAs/SM
// PHASE 0: A = g_x16 gathered via g_s2t, fused SwiGLU -> g_h (fp16)
// PHASE 1: A = g_h, epilogue: atomicAdd(out[tok], w * d)  (fused combine)
#define TILEB  16384
#define STAGE  (2*TILEB)
#define NSTG   3
#define GEMM_SMEM (NSTG*STAGE)       // 98304

template <int PHASE>
__global__ void __launch_bounds__(256, 2)
moe_gemm_kernel(float* __restrict__ out) {
    constexpr int Kd  = (PHASE == 0) ? D_HID : INTER;   // 2048 / 1408
    constexpr int NCH = Kd / 64;                        // 32 / 22
    constexpr int NROW = (PHASE == 0) ? NGU : D_HID;

    int e   = blockIdx.z;
    int cnt = g_count[e];
    int m0  = blockIdx.x * 128;
    if (m0 >= cnt) return;
    int n0  = blockIdx.y * 128;
    int off_e = expert_base(e);

    const __half* B = ((PHASE == 0) ? g_gup : g_dwn) + ((size_t)e * NROW + n0) * Kd;

    extern __shared__ __align__(128) char smem[];
    uint32_t sb = smem_u32(smem);

    int tid = threadIdx.x;
    int wid = tid >> 5;
    int lid = tid & 31;
    int warp_m = (wid >> 1) * 32;
    int warp_n = (wid & 1) * 64;

    // ---- hoisted cp.async indexing ----
    int rb = tid >> 3;
    int q  = tid & 7;
    uint32_t dstbase = (uint32_t)(rb * 128 + (((q ^ (rb & 7)) << 4)));
    const char* pa[4]; const char* pb[4]; uint32_t sza[4];
#pragma unroll
    for (int k = 0; k < 4; k++) {
        int r = rb + k * 32;
        bool v = (m0 + r) < cnt;
        sza[k] = v ? 16u : 0u;
        if (PHASE == 0) {
            int tok = v ? g_s2t[off_e + m0 + r] : 0;
            pa[k] = (const char*)(g_x16 + (size_t)tok * D_HID + q * 8);
        } else {
            pa[k] = (const char*)(g_h + (size_t)(off_e + m0 + r) * Kd + q * 8);
        }
        pb[k] = (const char*)(B + (size_t)r * Kd + q * 8);
    }

    // ---- hoisted ldsm bases ----
    uint32_t m7 = (uint32_t)(lid & 7) << 4;
    uint32_t a_base = (uint32_t)(warp_m + (lid & 15)) * 128 + m7;
    uint32_t a_dq   = (uint32_t)(lid >> 4);
    uint32_t b_base = (uint32_t)(warp_n + (lid & 7) + ((lid & 16) >> 1)) * 128 + m7;
    uint32_t b_dq   = (uint32_t)((lid >> 3) & 1);
    uint32_t a_s[4], b_s[4];
#pragma unroll
    for (int sl = 0; sl < 4; sl++) {
        a_s[sl] = a_base ^ ((uint32_t)(2*sl + a_dq) << 4);
        b_s[sl] = (b_base ^ ((uint32_t)(2*sl + b_dq) << 4)) + TILEB;
    }

    float d[2][8][4];
#pragma unroll
    for (int mi = 0; mi < 2; mi++)
#pragma unroll
        for (int ni = 0; ni < 8; ni++)
#pragma unroll
            for (int k = 0; k < 4; k++) d[mi][ni][k] = 0.f;

    auto load_chunk = [&](int ci, int s) {
        uint32_t st = sb + s * STAGE;
        size_t go = (size_t)ci * 128;
#pragma unroll
        for (int k = 0; k < 4; k++) {
            uint32_t dst = st + dstbase + (uint32_t)k * 4096;
            cp16z(dst,         pa[k] + go, sza[k]);
            cp16z(dst + TILEB, pb[k] + go, 16u);
        }
    };

    load_chunk(0, 0);
    asm volatile("cp.async.commit_group;" ::: "memory");
    if (NCH > 1) load_chunk(1, 1);
    asm volatile("cp.async.commit_group;" ::: "memory");

    int sidx = 0, lidx = 2;
#pragma unroll 1
    for (int i = 0; i < NCH; i++) {
        if (i == NCH - 1) {
            asm volatile("cp.async.wait_group 0;" ::: "memory");
        } else {
            asm volatile("cp.async.wait_group 1;" ::: "memory");
        }
        __syncthreads();
        if (i + 2 < NCH) {
            load_chunk(i + 2, lidx);
            asm volatile("cp.async.commit_group;" ::: "memory");
        }
        uint32_t st = sb + sidx * STAGE;
#pragma unroll
        for (int sl = 0; sl < 4; sl++) {
            uint32_t af[2][4];
            ldsm4(af[0], st + a_s[sl]);
            ldsm4(af[1], st + a_s[sl] + 2048);
#pragma unroll
            for (int pp = 0; pp < 2; pp++) {
                uint32_t bf[2][4];
                ldsm4(bf[0], st + b_s[sl] + (uint32_t)(pp*2 + 0) * 2048);
                ldsm4(bf[1], st + b_s[sl] + (uint32_t)(pp*2 + 1) * 2048);
#pragma unroll
                for (int mi = 0; mi < 2; mi++)
#pragma unroll
                    for (int qq = 0; qq < 4; qq++)
                        mma_f16(d[mi][pp*4 + qq], af[mi], &bf[qq >> 1][(qq & 1) * 2]);
            }
        }
        sidx = (sidx == NSTG-1) ? 0 : sidx + 1;
        lidx = (lidx == NSTG-1) ? 0 : lidx + 1;
    }

    // ---------------- epilogue ----------------
    if (PHASE == 0) {
        int icb = blockIdx.y * 64 + (warp_n >> 1);
#pragma unroll
        for (int mi = 0; mi < 2; mi++) {
            int rA = warp_m + mi * 16 + (lid >> 2);
            int rB = rA + 8;
            bool vA = (m0 + rA) < cnt;
            bool vB = (m0 + rB) < cnt;
            size_t rowA = (size_t)(off_e + m0 + rA);
            size_t rowB = (size_t)(off_e + m0 + rB);
#pragma unroll
            for (int ni = 0; ni < 4; ni++) {
                int col = icb + ni * 8 + (lid & 3) * 2;
                const float* g = d[mi][ni];
                const float* u = d[mi][ni + 4];
                if (vA) {
                    float h0 = g[0] / (1.f + expf(-g[0])) * u[0];
                    float h1 = g[1] / (1.f + expf(-g[1])) * u[1];
                    *(__half2*)(g_h + rowA * INTER + col) = __floats2half2_rn(h0, h1);
                }
                if (vB) {
                    float h0 = g[2] / (1.f + expf(-g[2])) * u[2];
                    float h1 = g[3] / (1.f + expf(-g[3])) * u[3];
                    *(__half2*)(g_h + rowB * INTER + col) = __floats2half2_rn(h0, h1);
                }
            }
        }
    } else {
#pragma unroll
        for (int mi = 0; mi < 2; mi++) {
            int rA = warp_m + mi * 16 + (lid >> 2);
            int rB = rA + 8;
            bool vA = (m0 + rA) < cnt;
            bool vB = (m0 + rB) < cnt;
            int sA = off_e + m0 + rA;
            int sB = off_e + m0 + rB;
            float wA = vA ? g_swt[sA] : 0.f;
            float wB = vB ? g_swt[sB] : 0.f;
            int tokA = vA ? g_s2t[sA] : 0;
            int tokB = vB ? g_s2t[sB] : 0;
            float* oA = out + (size_t)tokA * D_HID + n0 + warp_n + (lid & 3) * 2;
            float* oB = out + (size_t)tokB * D_HID + n0 + warp_n + (lid & 3) * 2;
#pragma unroll
            for (int ni = 0; ni < 8; ni++) {
                if (vA) atomicAdd((float2*)(oA + ni * 8),
                                  make_float2(wA * d[mi][ni][0], wA * d[mi][ni][1]));
                if (vB) atomicAdd((float2*)(oB + ni * 8),
                                  make_float2(wB * d[mi][ni][2], wB * d[mi][ni][3]));
            }
        }
    }
}

// ---------------- launch ----------------
extern "C" void kernel_launch(void* const* d_in, const int* in_sizes, int n_in,
                              void* d_out, int out_size) {
    const float* x   = (const float*)d_in[0];
    const float* rw  = (const float*)d_in[1];
    const float* gup = (const float*)d_in[2];
    const float* dwn = (const float*)d_in[3];
    float* out = (float*)d_out;
    int T = in_sizes[0] / D_HID;
    int n4 = (T * D_HID) / 4;

    cudaFuncSetAttribute(moe_gemm_kernel<0>, cudaFuncAttributeMaxDynamicSharedMemorySize, GEMM_SMEM);
    cudaFuncSetAttribute(moe_gemm_kernel<1>, cudaFuncAttributeMaxDynamicSharedMemorySize, GEMM_SMEM);

    zero_kernel<<<(n4 + 255) / 256, 256>>>((float4*)out, n4);          // 0
    int pr_blocks = GUP_ROWS + DWN_ROWS + T;                            // 43008
    prep_router_kernel<<<pr_blocks, 256>>>(x, rw, gup, dwn);            // 1
    map_kernel<<<TPAIR / 256, 256>>>();                                 // 2

    dim3 g0(32, NGU / 128, NEXP);                                       // 3 (GEMM1)
    moe_gemm_kernel<0><<<g0, 256, GEMM_SMEM>>>(nullptr);

    dim3 g1(32, D_HID / 128, NEXP);                                     // 4 (GEMM2 + combine)
    moe_gemm_kernel<1><<<g1, 256, GEMM_SMEM>>>(out);
}

// round 16
// speedup vs baseline: 1.0051x; 1.0051x over previous
#include <cuda_runtime.h>
#include <cuda_fp16.h>
#include <cstdint>
#include <math.h>

#define D_HID 2048
#define INTER 1408
#define NGU   2816
#define NEXP  8
#define TMAX  4096
#define TPAIR 8192
#define RMAX  9216

// ---------------- device scratch ----------------
__device__ int   g_count[NEXP];
__device__ int   g_top_e[TPAIR];
__device__ int   g_pos[TPAIR];
__device__ int   g_p2s[TPAIR];
__device__ int   g_s2t[RMAX];
__device__ float g_wt[TPAIR];
__device__ __align__(256) __half g_x16 [(size_t)TMAX * D_HID];
__device__ __align__(256) __half g_gup [(size_t)NEXP * NGU * D_HID];
__device__ __align__(256) __half g_dwn [(size_t)NEXP * D_HID * INTER];
__device__ __align__(256) __half g_h   [(size_t)RMAX * INTER];
__device__ __align__(256) __half g_ct  [(size_t)RMAX * D_HID];

// ---------------- helpers ----------------
__device__ __forceinline__ uint32_t smem_u32(const void* p) {
    uint32_t a;
    asm("{ .reg .u64 t; cvta.to.shared.u64 t, %1; cvt.u32.u64 %0, t; }" : "=r"(a) : "l"(p));
    return a;
}
__device__ __forceinline__ void cp16z(uint32_t dst, const void* src, uint32_t sz) {
    asm volatile("cp.async.cg.shared.global [%0], [%1], 16, %2;"
                 :: "r"(dst), "l"(src), "r"(sz));
}
__device__ __forceinline__ void ldsm4(uint32_t* r, uint32_t addr) {
    asm volatile("ldmatrix.sync.aligned.m8n8.x4.shared.b16 {%0,%1,%2,%3}, [%4];"
                 : "=r"(r[0]), "=r"(r[1]), "=r"(r[2]), "=r"(r[3]) : "r"(addr));
}
__device__ __forceinline__ void mma_f16(float* d, const uint32_t* a, const uint32_t* b) {
    asm volatile("mma.sync.aligned.m16n8k16.row.col.f32.f16.f16.f32 "
                 "{%0,%1,%2,%3}, {%4,%5,%6,%7}, {%8,%9}, {%0,%1,%2,%3};"
                 : "+f"(d[0]), "+f"(d[1]), "+f"(d[2]), "+f"(d[3])
                 : "r"(a[0]), "r"(a[1]), "r"(a[2]), "r"(a[3]), "r"(b[0]), "r"(b[1]));
}
__device__ __forceinline__ int expert_base(int e) {
    int o = 0;
#pragma unroll
    for (int k = 0; k < NEXP; k++)
        if (k < e) o += (g_count[k] + 127) & ~127;
    return o;
}
__device__ __forceinline__ uint4 pack8(float4 a, float4 b) {
    uint4 o;
    __half2 h0 = __floats2half2_rn(a.x, a.y);
    __half2 h1 = __floats2half2_rn(a.z, a.w);
    __half2 h2 = __floats2half2_rn(b.x, b.y);
    __half2 h3 = __floats2half2_rn(b.z, b.w);
    o.x = *reinterpret_cast<uint32_t*>(&h0);
    o.y = *reinterpret_cast<uint32_t*>(&h1);
    o.z = *reinterpret_cast<uint32_t*>(&h2);
    o.w = *reinterpret_cast<uint32_t*>(&h3);
    return o;
}

// ---------------- init ----------------
__global__ void zero_counts_kernel() {
    if (threadIdx.x < NEXP) g_count[threadIdx.x] = 0;
}

// ---------------- router (vectorized, fused x->fp16) ----------------
__global__ void router_kernel(const float* __restrict__ x,
                              const float* __restrict__ rw) {
    int t = blockIdx.x;
    int tid = threadIdx.x;               // 256; each thread owns 8 elems
    const float4* x4 = (const float4*)(x + (size_t)t * D_HID);
    float4 v0 = x4[2*tid];
    float4 v1 = x4[2*tid + 1];
    ((uint4*)(g_x16 + (size_t)t * D_HID))[tid] = pack8(v0, v1);

    float p[NEXP];
#pragma unroll
    for (int e = 0; e < NEXP; e++) {
        const float4* r4 = (const float4*)(rw + (size_t)e * D_HID);
        float4 w0 = r4[2*tid];
        float4 w1 = r4[2*tid + 1];
        float s = v0.x * w0.x;
        s = fmaf(v0.y, w0.y, s);
        s = fmaf(v0.z, w0.z, s);
        s = fmaf(v0.w, w0.w, s);
        s = fmaf(v1.x, w1.x, s);
        s = fmaf(v1.y, w1.y, s);
        s = fmaf(v1.z, w1.z, s);
        s = fmaf(v1.w, w1.w, s);
        p[e] = s;
    }
#pragma unroll
    for (int off = 16; off > 0; off >>= 1)
#pragma unroll
        for (int e = 0; e < NEXP; e++)
            p[e] += __shfl_down_sync(0xffffffffu, p[e], off);
    __shared__ float s[8][NEXP];
    int warp = tid >> 5;
    if ((tid & 31) == 0)
#pragma unroll
        for (int e = 0; e < NEXP; e++) s[warp][e] = p[e];
    __syncthreads();
    if (tid == 0) {
        float l[NEXP];
#pragma unroll
        for (int e = 0; e < NEXP; e++) {
            float a = 0.f;
#pragma unroll
            for (int w = 0; w < 8; w++) a += s[w][e];
            l[e] = a;
        }
        int i0 = 0;
#pragma unroll
        for (int e = 1; e < NEXP; e++) if (l[e] > l[i0]) i0 = e;
        int i1 = (i0 == 0) ? 1 : 0;
#pragma unroll
        for (int e = 0; e < NEXP; e++)
            if (e != i0 && l[e] > l[i1]) i1 = e;
        float e1  = expf(l[i1] - l[i0]);
        float inv = 1.f / (1.f + e1);
        g_wt[2*t]   = inv;
        g_wt[2*t+1] = e1 * inv;
        int p0 = atomicAdd(&g_count[i0], 1);
        g_top_e[2*t] = i0; g_pos[2*t] = p0;
        int p1 = atomicAdd(&g_count[i1], 1);
        g_top_e[2*t+1] = i1; g_pos[2*t+1] = p1;
    }
}

// ---------------- prep: gup conversion (16B stores) + maps ----------------
#define GUP_ROWS (NEXP*NGU)    // 22528
#define DWN_ROWS (NEXP*D_HID)  // 16384
#define MAP_BLKS (TPAIR/256)   // 32
__global__ void prep_kernel(const float* __restrict__ gup) {
    int b = blockIdx.x;
    int i = threadIdx.x;       // 256
    if (b < GUP_ROWS) {
        int e = b / NGU;
        int n = b % NGU;
        int blk = n >> 6, r = n & 63;
        int src_n = (r < 32) ? (blk*32 + r) : (INTER + blk*32 + (r - 32));
        const float4* src = (const float4*)(gup + ((size_t)e * NGU + src_n) * D_HID);
        float4 a = src[2*i], c = src[2*i + 1];
        ((uint4*)(g_gup + (size_t)b * D_HID))[i] = pack8(a, c);
    } else {
        int p = (b - GUP_ROWS) * 256 + i;
        if (p < TPAIR) {
            int sidx = expert_base(g_top_e[p]) + g_pos[p];
            g_p2s[p] = sidx;
            g_s2t[sidx] = p >> 1;
        }
    }
}

// ---------------- HMMA grouped GEMM (pure fp16, SW128, hoisted indexing) ---
// CTA tile 128x128, 256 threads (8 warps: 4 in M x 2 in N), 2 CTAs/SM
// PHASE 0: every CTA first converts 3 dwn rows fp32->fp16 (fills g_dwn for
//          GEMM2), then A = g_x16 gathered via g_s2t, fused SwiGLU -> g_h
// PHASE 1: A = g_h (slot order), fp16 epilogue -> g_ct
#define TILEB  16384
#define STAGE  (2*TILEB)
#define NSTG   3
#define GEMM_SMEM (NSTG*STAGE)       // 98304

template <int PHASE>
__global__ void __launch_bounds__(256, 2)
moe_gemm_kernel(const float* __restrict__ dwn) {
    constexpr int Kd  = (PHASE == 0) ? D_HID : INTER;   // 2048 / 1408
    constexpr int NCH = Kd / 64;                        // 32 / 22
    constexpr int NROW = (PHASE == 0) ? NGU : D_HID;

    int tid = threadIdx.x;

    // ---- fused dwn conversion (PHASE 0 only; all CTAs, incl. idle) ----
    if (PHASE == 0) {
        int fid = (blockIdx.z * gridDim.y + blockIdx.y) * gridDim.x + blockIdx.x;
        int row0 = fid * 3;
#pragma unroll
        for (int rr = 0; rr < 3; rr++) {
            int row = row0 + rr;
            if (row < DWN_ROWS) {
                const float4* src = (const float4*)(dwn + (size_t)row * INTER);
                uint4* dst = (uint4*)(g_dwn + (size_t)row * INTER);
                for (int j = tid; j < INTER/8; j += 256) {
                    float4 a = src[2*j], c = src[2*j + 1];
                    dst[j] = pack8(a, c);
                }
            }
        }
    }

    int e   = blockIdx.z;
    int cnt = g_count[e];
    int m0  = blockIdx.x * 128;
    if (m0 >= cnt) return;
    int n0  = blockIdx.y * 128;
    int off_e = expert_base(e);

    const __half* B = ((PHASE == 0) ? g_gup : g_dwn) + ((size_t)e * NROW + n0) * Kd;

    extern __shared__ __align__(128) char smem[];
    uint32_t sb = smem_u32(smem);

    int wid = tid >> 5;
    int lid = tid & 31;
    int warp_m = (wid >> 1) * 32;
    int warp_n = (wid & 1) * 64;

    // ---- hoisted cp.async indexing ----
    int rb = tid >> 3;
    int q  = tid & 7;
    uint32_t dstbase = (uint32_t)(rb * 128 + (((q ^ (rb & 7)) << 4)));
    const char* pa[4]; const char* pb[4]; uint32_t sza[4];
#pragma unroll
    for (int k = 0; k < 4; k++) {
        int r = rb + k * 32;
        bool v = (m0 + r) < cnt;
        sza[k] = v ? 16u : 0u;
        if (PHASE == 0) {
            int tok = v ? g_s2t[off_e + m0 + r] : 0;
            pa[k] = (const char*)(g_x16 + (size_t)tok * D_HID + q * 8);
        } else {
            pa[k] = (const char*)(g_h + (size_t)(off_e + m0 + r) * Kd + q * 8);
        }
        pb[k] = (const char*)(B + (size_t)r * Kd + q * 8);
    }

    // ---- hoisted ldsm bases ----
    uint32_t m7 = (uint32_t)(lid & 7) << 4;
    uint32_t a_base = (uint32_t)(warp_m + (lid & 15)) * 128 + m7;
    uint32_t a_dq   = (uint32_t)(lid >> 4);
    uint32_t b_base = (uint32_t)(warp_n + (lid & 7) + ((lid & 16) >> 1)) * 128 + m7;
    uint32_t b_dq   = (uint32_t)((lid >> 3) & 1);
    uint32_t a_s[4], b_s[4];
#pragma unroll
    for (int sl = 0; sl < 4; sl++) {
        a_s[sl] = a_base ^ ((uint32_t)(2*sl + a_dq) << 4);
        b_s[sl] = (b_base ^ ((uint32_t)(2*sl + b_dq) << 4)) + TILEB;
    }

    float d[2][8][4];
#pragma unroll
    for (int mi = 0; mi < 2; mi++)
#pragma unroll
        for (int ni = 0; ni < 8; ni++)
#pragma unroll
            for (int k = 0; k < 4; k++) d[mi][ni][k] = 0.f;

    auto load_chunk = [&](int ci, int s) {
        uint32_t st = sb + s * STAGE;
        size_t go = (size_t)ci * 128;
#pragma unroll
        for (int k = 0; k < 4; k++) {
            uint32_t dst = st + dstbase + (uint32_t)k * 4096;
            cp16z(dst,         pa[k] + go, sza[k]);
            cp16z(dst + TILEB, pb[k] + go, 16u);
        }
    };

    load_chunk(0, 0);
    asm volatile("cp.async.commit_group;" ::: "memory");
    if (NCH > 1) load_chunk(1, 1);
    asm volatile("cp.async.commit_group;" ::: "memory");

    int sidx = 0, lidx = 2;
#pragma unroll 1
    for (int i = 0; i < NCH; i++) {
        if (i == NCH - 1) {
            asm volatile("cp.async.wait_group 0;" ::: "memory");
        } else {
            asm volatile("cp.async.wait_group 1;" ::: "memory");
        }
        __syncthreads();
        if (i + 2 < NCH) {
            load_chunk(i + 2, lidx);
            asm volatile("cp.async.commit_group;" ::: "memory");
        }
        uint32_t st = sb + sidx * STAGE;
#pragma unroll
        for (int sl = 0; sl < 4; sl++) {
            uint32_t af[2][4];
            ldsm4(af[0], st + a_s[sl]);
            ldsm4(af[1], st + a_s[sl] + 2048);
#pragma unroll
            for (int pp = 0; pp < 2; pp++) {
                uint32_t bf[2][4];
                ldsm4(bf[0], st + b_s[sl] + (uint32_t)(pp*2 + 0) * 2048);
                ldsm4(bf[1], st + b_s[sl] + (uint32_t)(pp*2 + 1) * 2048);
#pragma unroll
                for (int mi = 0; mi < 2; mi++)
#pragma unroll
                    for (int qq = 0; qq < 4; qq++)
                        mma_f16(d[mi][pp*4 + qq], af[mi], &bf[qq >> 1][(qq & 1) * 2]);
            }
        }
        sidx = (sidx == NSTG-1) ? 0 : sidx + 1;
        lidx = (lidx == NSTG-1) ? 0 : lidx + 1;
    }

    // ---------------- epilogue ----------------
    if (PHASE == 0) {
        int icb = blockIdx.y * 64 + (warp_n >> 1);
#pragma unroll
        for (int mi = 0; mi < 2; mi++) {
            int rA = warp_m + mi * 16 + (lid >> 2);
            int rB = rA + 8;
            bool vA = (m0 + rA) < cnt;
            bool vB = (m0 + rB) < cnt;
            size_t rowA = (size_t)(off_e + m0 + rA);
            size_t rowB = (size_t)(off_e + m0 + rB);
#pragma unroll
            for (int ni = 0; ni < 4; ni++) {
                int col = icb + ni * 8 + (lid & 3) * 2;
                const float* g = d[mi][ni];
                const float* u = d[mi][ni + 4];
                if (vA) {
                    float h0 = g[0] / (1.f + expf(-g[0])) * u[0];
                    float h1 = g[1] / (1.f + expf(-g[1])) * u[1];
                    *(__half2*)(g_h + rowA * INTER + col) = __floats2half2_rn(h0, h1);
                }
                if (vB) {
                    float h0 = g[2] / (1.f + expf(-g[2])) * u[2];
                    float h1 = g[3] / (1.f + expf(-g[3])) * u[3];
                    *(__half2*)(g_h + rowB * INTER + col) = __floats2half2_rn(h0, h1);
                }
            }
        }
    } else {
#pragma unroll
        for (int mi = 0; mi < 2; mi++) {
            int rA = warp_m + mi * 16 + (lid >> 2);
            int rB = rA + 8;
            bool vA = (m0 + rA) < cnt;
            bool vB = (m0 + rB) < cnt;
            __half* cA = g_ct + (size_t)(off_e + m0 + rA) * D_HID + n0 + warp_n + (lid & 3) * 2;
            __half* cB = g_ct + (size_t)(off_e + m0 + rB) * D_HID + n0 + warp_n + (lid & 3) * 2;
#pragma unroll
            for (int ni = 0; ni < 8; ni++) {
                if (vA) *(__half2*)(cA + ni * 8) =
                    __floats2half2_rn(d[mi][ni][0], d[mi][ni][1]);
                if (vB) *(__half2*)(cB + ni * 8) =
                    __floats2half2_rn(d[mi][ni][2], d[mi][ni][3]);
            }
        }
    }
}

// ---------------- combine (fp16 ct) ----------------
__global__ void combine_kernel(float* __restrict__ out, int total4) {
    int i = blockIdx.x * blockDim.x + threadIdx.x;
    if (i >= total4) return;
    int c = i % (D_HID/4);
    int t = i / (D_HID/4);
    float w0 = g_wt[2*t], w1 = g_wt[2*t+1];
    int s0 = g_p2s[2*t], s1 = g_p2s[2*t+1];
    const __half2* p0 = (const __half2*)(g_ct + (size_t)s0 * D_HID) + 2*c;
    const __half2* p1 = (const __half2*)(g_ct + (size_t)s1 * D_HID) + 2*c;
    float2 a0 = __half22float2(p0[0]);
    float2 a1 = __half22float2(p0[1]);
    float2 b0 = __half22float2(p1[0]);
    float2 b1 = __half22float2(p1[1]);
    float4 o;
    o.x = fmaf(w0, a0.x, w1 * b0.x);
    o.y = fmaf(w0, a0.y, w1 * b0.y);
    o.z = fmaf(w0, a1.x, w1 * b1.x);
    o.w = fmaf(w0, a1.y, w1 * b1.y);
    ((float4*)out)[i] = o;
}

// ---------------- launch ----------------
extern "C" void kernel_launch(void* const* d_in, const int* in_sizes, int n_in,
                              void* d_out, int out_size) {
    const float* x   = (const float*)d_in[0];
    const float* rw  = (const float*)d_in[1];
    const float* gup = (const float*)d_in[2];
    const float* dwn = (const float*)d_in[3];
    float* out = (float*)d_out;
    int T = in_sizes[0] / D_HID;

    cudaFuncSetAttribute(moe_gemm_kernel<0>, cudaFuncAttributeMaxDynamicSharedMemorySize, GEMM_SMEM);
    cudaFuncSetAttribute(moe_gemm_kernel<1>, cudaFuncAttributeMaxDynamicSharedMemorySize, GEMM_SMEM);

    zero_counts_kernel<<<1, 32>>>();                       // 0
    router_kernel<<<T, 256>>>(x, rw);                      // 1
    int prep_blocks = GUP_ROWS + MAP_BLKS;                 // 22560
    prep_kernel<<<prep_blocks, 256>>>(gup);                // 2

    dim3 g0(32, NGU / 128, NEXP);                          // 3 (GEMM1 + dwn conv)
    moe_gemm_kernel<0><<<g0, 256, GEMM_SMEM>>>(dwn);

    dim3 g1(32, D_HID / 128, NEXP);                        // 4
    moe_gemm_kernel<1><<<g1, 256, GEMM_SMEM>>>(nullptr);

    combine_kernel<<<(T * (D_HID/4) + 255) / 256, 256>>>(out, T * (D_HID/4)); // 5
}